// round 14
// baseline (speedup 1.0000x reference)
#include <cuda_runtime.h>
#include <cuda_fp16.h>
#include <mma.h>
#include <math.h>

using namespace nvcuda;

#define NN 50000
#define EE 800000
#define ETOT (EE + NN)
#define GG 64

// ---------------- scratch ----------------
__device__ __half2 d_h2[NN * 48];   // fp16 message matrix (H), 48 half2 per row
__device__ float d_o[NN * 96];
__device__ float d_as[NN * 4];
__device__ float d_ad[NN * 4];
__device__ int   d_deg[NN];
__device__ int   d_part[NN];
__device__ int   d_bsum[64];
__device__ int   d_off[NN + 1];
__device__ int   d_srcs[ETOT];
__device__ float d_gate[NN];
__device__ float d_gm[GG];
__device__ float d_gden[GG];
__device__ float d_pool[GG * 8 * 96];

__device__ __forceinline__ void atomicMaxF(float* a, float v) {
    if (v >= 0.f) atomicMax((int*)a, __float_as_int(v));
    else          atomicMin((unsigned int*)a, __float_as_uint(v));
}

typedef unsigned long long ull;
__device__ __forceinline__ ull pk2(float x, float y) {
    ull r;
    asm("mov.b64 %0, {%1, %2};" : "=l"(r) : "f"(x), "f"(y));
    return r;
}
__device__ __forceinline__ ull fma2(ull a, ull b, ull c) {
    ull d;
    asm("fma.rn.f32x2 %0, %1, %2, %3;" : "=l"(d) : "l"(a), "l"(b), "l"(c));
    return d;
}
__device__ __forceinline__ void upk2(ull v, float& x, float& y) {
    asm("mov.b64 {%0, %1}, %2;" : "=f"(x), "=f"(y) : "l"(v));
}

// ================= CSR build =================
__global__ void k_hist(const int* __restrict__ ei, int* __restrict__ deg, int etot, int eraw) {
    int e = blockIdx.x * blockDim.x + threadIdx.x;
    if (e >= etot) return;
    int d = (e < eraw) ? __ldg(&ei[eraw + e]) : e - eraw;
    atomicAdd(&deg[d], 1);
}

__global__ void k_scanA(const int* __restrict__ deg, int* __restrict__ part,
                        int* __restrict__ bsum, int n) {
    __shared__ int wsum[32];
    int t = threadIdx.x;
    int i = blockIdx.x * 1024 + t;
    int v = (i < n) ? deg[i] : 0;
    int lane = t & 31, w = t >> 5;
    int x = v;
#pragma unroll
    for (int o = 1; o < 32; o <<= 1) {
        int y = __shfl_up_sync(0xffffffffu, x, o);
        if (lane >= o) x += y;
    }
    if (lane == 31) wsum[w] = x;
    __syncthreads();
    if (w == 0) {
        int s = wsum[lane];
#pragma unroll
        for (int o = 1; o < 32; o <<= 1) {
            int y = __shfl_up_sync(0xffffffffu, s, o);
            if (lane >= o) s += y;
        }
        wsum[lane] = s;
    }
    __syncthreads();
    int woff = (w > 0) ? wsum[w - 1] : 0;
    if (i < n) part[i] = x - v + woff;
    if (t == 0) bsum[blockIdx.x] = wsum[31];
}

__global__ void k_scanB(int* __restrict__ bsum, int nb) {
    __shared__ int w0tot;
    int t = threadIdx.x;
    int lane = t & 31, w = t >> 5;
    int v = (t < nb) ? bsum[t] : 0;
    int x = v;
#pragma unroll
    for (int o = 1; o < 32; o <<= 1) {
        int y = __shfl_up_sync(0xffffffffu, x, o);
        if (lane >= o) x += y;
    }
    if (w == 0 && lane == 31) w0tot = x;
    __syncthreads();
    if (w == 1) x += w0tot;
    if (t < nb) bsum[t] = x - v;
}

__global__ void k_scanC(const int* __restrict__ part, const int* __restrict__ bsum,
                        int* __restrict__ off, int* __restrict__ cur,
                        float* __restrict__ GM, float* __restrict__ GDEN,
                        int n, int etot) {
    int i = blockIdx.x * 1024 + threadIdx.x;
    if (i < n) {
        int v = part[i] + bsum[blockIdx.x];
        off[i] = v;
        cur[i] = v;
    }
    if (i == 0) off[n] = etot;
    if (blockIdx.x == 0 && threadIdx.x < GG) {
        GM[threadIdx.x] = -INFINITY;
        GDEN[threadIdx.x] = 0.f;
    }
}

__global__ void k_scatter(const int* __restrict__ ei, int* __restrict__ cur,
                          int* __restrict__ srcs, int etot, int eraw) {
    int e = blockIdx.x * blockDim.x + threadIdx.x;
    if (e >= etot) return;
    int s, d;
    if (e < eraw) { s = __ldg(&ei[e]); d = __ldg(&ei[eraw + e]); }
    else          { s = d = e - eraw; }
    int pos = atomicAdd(&cur[d], 1);
    srcs[pos] = s;
}

// ================= Tensor-core GEMM + fused alpha epilogue =================
template<int K>
__global__ void __launch_bounds__(256, 2) k_gemmT(const float* __restrict__ A,
                                                  const float* __restrict__ W,
                                                  const float* __restrict__ asrc,
                                                  const float* __restrict__ adst,
                                                  __half2* __restrict__ H2,
                                                  float* __restrict__ AS,
                                                  float* __restrict__ AD, int n) {
    extern __shared__ char smc[];
    const int SA = K + 8, SB = 104, SC = 100;
    __half* Ah = (__half*)smc;                    // 128 x SA
    __half* Wh = (__half*)smc + 128 * SA;         // K x SB
    float*  Cs = (float*)smc;                     // alias: 128 x SC
    __shared__ float s_as[96], s_ad[96];

    int tid = threadIdx.x, w = tid >> 5;
    int row0 = blockIdx.x * 128;

    if (tid < 96) { s_as[tid] = __ldg(&asrc[tid]); s_ad[tid] = __ldg(&adst[tid]); }

    for (int i = tid; i < 128 * K; i += 256) {
        int r = i / K, c = i - r * K;
        int row = row0 + r;
        Ah[r * SA + c] = (row < n) ? __float2half(A[(size_t)row * K + c]) : __half(0.f);
    }
    for (int i = tid; i < K * 96; i += 256) {
        int k = i / 96, c = i - k * 96;
        Wh[k * SB + c] = __float2half(W[i]);
    }
    __syncthreads();

    wmma::fragment<wmma::accumulator, 16, 16, 16, float> cf[6];
#pragma unroll
    for (int cg = 0; cg < 6; cg++) wmma::fill_fragment(cf[cg], 0.f);
    wmma::fragment<wmma::matrix_a, 16, 16, 16, __half, wmma::row_major> af;
    wmma::fragment<wmma::matrix_b, 16, 16, 16, __half, wmma::row_major> bf;
#pragma unroll
    for (int ks = 0; ks < K / 16; ks++) {
        wmma::load_matrix_sync(af, Ah + w * 16 * SA + ks * 16, SA);
#pragma unroll
        for (int cg = 0; cg < 6; cg++) {
            wmma::load_matrix_sync(bf, Wh + ks * 16 * SB + cg * 16, SB);
            wmma::mma_sync(cf[cg], af, bf, cf[cg]);
        }
    }
    __syncthreads();
#pragma unroll
    for (int cg = 0; cg < 6; cg++)
        wmma::store_matrix_sync(Cs + w * 16 * SC + cg * 16, cf[cg], SC, wmma::mem_row_major);
    __syncthreads();

    int row = tid >> 1, hv = tid & 1;
    int grow = row0 + row;
    if (grow < n) {
        const float* cr = Cs + row * SC + hv * 48;
        int h0 = hv * 2;
        const float* as0 = s_as + h0 * 24;
        const float* ad0 = s_ad + h0 * 24;
        union { __half2 h[24]; uint4 u[6]; } pk;
        float sp0 = 0.f, dp0 = 0.f, sp1 = 0.f, dp1 = 0.f;
#pragma unroll
        for (int j = 0; j < 12; j++) {
            float ca = cr[2 * j], cb = cr[2 * j + 1];
            pk.h[j] = __floats2half2_rn(ca, cb);
            sp0 += ca * as0[2 * j] + cb * as0[2 * j + 1];
            dp0 += ca * ad0[2 * j] + cb * ad0[2 * j + 1];
        }
#pragma unroll
        for (int j = 12; j < 24; j++) {
            float ca = cr[2 * j], cb = cr[2 * j + 1];
            pk.h[j] = __floats2half2_rn(ca, cb);
            int jj = 2 * j - 24;
            sp1 += ca * as0[24 + jj] + cb * as0[24 + jj + 1];
            dp1 += ca * ad0[24 + jj] + cb * ad0[24 + jj + 1];
        }
        uint4* dst = (uint4*)(H2 + (size_t)grow * 48 + hv * 24);
#pragma unroll
        for (int q = 0; q < 6; q++) dst[q] = pk.u[q];
        AS[grow * 4 + h0]     = sp0;
        AS[grow * 4 + h0 + 1] = sp1;
        AD[grow * 4 + h0]     = dp0;
        AD[grow * 4 + h0 + 1] = dp1;
    }
}

// ================= fused softmax + aggregation (warp per dst, dual-edge uint4 gather) =================
#define DCAP 128
__global__ void k_sagg(const int* __restrict__ off, const int* __restrict__ srcs,
                       const float* __restrict__ AS, const float* __restrict__ AD,
                       const __half2* __restrict__ H2, const float* __restrict__ bias,
                       float* __restrict__ OUT, int n) {
    __shared__ int    ssrc[8][DCAP];
    __shared__ float4 slog[8][DCAP];
    int gtid = blockIdx.x * blockDim.x + threadIdx.x;
    int node = gtid >> 5, lane = gtid & 31;
    int ws = threadIdx.x >> 5;
    if (node >= n) return;
    int beg = __ldg(&off[node]), end = __ldg(&off[node + 1]);
    int deg = end - beg;
    float4 ad = *(const float4*)(AD + node * 4);

    float4 den = make_float4(0.f, 0.f, 0.f, 0.f);
    float4 mx = make_float4(-INFINITY, -INFINITY, -INFINITY, -INFINITY);

    if (deg <= DCAP) {
        // ---- pass 1: gather once, cache src + logits, max ----
        for (int j = lane; j < deg; j += 32) {
            int s = __ldg(&srcs[beg + j]);
            float4 a = *(const float4*)(AS + s * 4);
            float t; float4 v;
            t = a.x + ad.x; v.x = t > 0.f ? t : 0.2f * t; mx.x = fmaxf(mx.x, v.x);
            t = a.y + ad.y; v.y = t > 0.f ? t : 0.2f * t; mx.y = fmaxf(mx.y, v.y);
            t = a.z + ad.z; v.z = t > 0.f ? t : 0.2f * t; mx.z = fmaxf(mx.z, v.z);
            t = a.w + ad.w; v.w = t > 0.f ? t : 0.2f * t; mx.w = fmaxf(mx.w, v.w);
            ssrc[ws][j] = s;
            slog[ws][j] = v;
        }
#pragma unroll
        for (int o = 16; o > 0; o >>= 1) {
            mx.x = fmaxf(mx.x, __shfl_xor_sync(0xffffffffu, mx.x, o));
            mx.y = fmaxf(mx.y, __shfl_xor_sync(0xffffffffu, mx.y, o));
            mx.z = fmaxf(mx.z, __shfl_xor_sync(0xffffffffu, mx.z, o));
            mx.w = fmaxf(mx.w, __shfl_xor_sync(0xffffffffu, mx.w, o));
        }
        __syncwarp();
        // ---- pass 2a: exp + denominator ----
        for (int j = lane; j < deg; j += 32) {
            float4 v = slog[ws][j];
            float4 ex;
            ex.x = __expf(v.x - mx.x); ex.y = __expf(v.y - mx.y);
            ex.z = __expf(v.z - mx.z); ex.w = __expf(v.w - mx.w);
            slog[ws][j] = ex;
            den.x += ex.x; den.y += ex.y; den.z += ex.z; den.w += ex.w;
        }
        __syncwarp();
#pragma unroll
        for (int o = 16; o > 0; o >>= 1) {
            den.x += __shfl_xor_sync(0xffffffffu, den.x, o);
            den.y += __shfl_xor_sync(0xffffffffu, den.y, o);
            den.z += __shfl_xor_sync(0xffffffffu, den.z, o);
            den.w += __shfl_xor_sync(0xffffffffu, den.w, o);
        }
        // ---- pass 2b: aggregation. 2 lane-groups of 12; uint4 loads (8 ch/lane) ----
        if (lane < 24) {
            int grp = lane >= 12;           // 0: even edges, 1: odd edges
            int sl  = grp ? lane - 12 : lane;   // 0..11, covers channels [sl*8, sl*8+8)
            int head = sl / 3;                  // 8 channels within one head (24%8==0)
            const float* sexf = (const float*)&slog[ws][0];
            float fa[8];
#pragma unroll
            for (int q = 0; q < 8; q++) fa[q] = 0.f;
#pragma unroll 2
            for (int j = grp; j < deg; j += 2) {
                int s = ssrc[ws][j];
                float wv = sexf[j * 4 + head];
                uint4 raw = __ldg((const uint4*)(H2 + s * 48) + sl);
                float2 f0 = __half22float2(*(__half2*)&raw.x);
                float2 f1 = __half22float2(*(__half2*)&raw.y);
                float2 f2 = __half22float2(*(__half2*)&raw.z);
                float2 f3 = __half22float2(*(__half2*)&raw.w);
                fa[0] = fmaf(f0.x, wv, fa[0]); fa[1] = fmaf(f0.y, wv, fa[1]);
                fa[2] = fmaf(f1.x, wv, fa[2]); fa[3] = fmaf(f1.y, wv, fa[3]);
                fa[4] = fmaf(f2.x, wv, fa[4]); fa[5] = fmaf(f2.y, wv, fa[5]);
                fa[6] = fmaf(f3.x, wv, fa[6]); fa[7] = fmaf(f3.y, wv, fa[7]);
            }
            // combine group1 into group0 (lane sl receives from lane sl+12)
#pragma unroll
            for (int q = 0; q < 8; q++) {
                float other = __shfl_sync(0x00ffffffu, fa[q], sl + 12);
                if (!grp) fa[q] += other;
            }
            if (!grp) {
                float dh = head == 0 ? den.x : (head == 1 ? den.y : (head == 2 ? den.z : den.w));
                float inv = 1.f / (dh + 1e-16f);
                float4 b0 = *(const float4*)(bias + sl * 8);
                float4 b1 = *(const float4*)(bias + sl * 8 + 4);
                float4 o0, o1;
                o0.x = fa[0] * inv + b0.x;  o0.x = o0.x > 0.f ? o0.x : expm1f(o0.x);
                o0.y = fa[1] * inv + b0.y;  o0.y = o0.y > 0.f ? o0.y : expm1f(o0.y);
                o0.z = fa[2] * inv + b0.z;  o0.z = o0.z > 0.f ? o0.z : expm1f(o0.z);
                o0.w = fa[3] * inv + b0.w;  o0.w = o0.w > 0.f ? o0.w : expm1f(o0.w);
                o1.x = fa[4] * inv + b1.x;  o1.x = o1.x > 0.f ? o1.x : expm1f(o1.x);
                o1.y = fa[5] * inv + b1.y;  o1.y = o1.y > 0.f ? o1.y : expm1f(o1.y);
                o1.z = fa[6] * inv + b1.z;  o1.z = o1.z > 0.f ? o1.z : expm1f(o1.z);
                o1.w = fa[7] * inv + b1.w;  o1.w = o1.w > 0.f ? o1.w : expm1f(o1.w);
                *(float4*)(OUT + node * 96 + sl * 8)     = o0;
                *(float4*)(OUT + node * 96 + sl * 8 + 4) = o1;
            }
        }
    } else {
        // ---- rare fallback: chunked recompute (old layout) ----
        bool act = lane < 24;
        int head = lane / 6;
        float4 acc = make_float4(0.f, 0.f, 0.f, 0.f);
        for (int e = beg + lane; e < end; e += 32) {
            int s = __ldg(&srcs[e]);
            float4 a = *(const float4*)(AS + s * 4);
            float t;
            t = a.x + ad.x; t = t > 0.f ? t : 0.2f * t; mx.x = fmaxf(mx.x, t);
            t = a.y + ad.y; t = t > 0.f ? t : 0.2f * t; mx.y = fmaxf(mx.y, t);
            t = a.z + ad.z; t = t > 0.f ? t : 0.2f * t; mx.z = fmaxf(mx.z, t);
            t = a.w + ad.w; t = t > 0.f ? t : 0.2f * t; mx.w = fmaxf(mx.w, t);
        }
#pragma unroll
        for (int o = 16; o > 0; o >>= 1) {
            mx.x = fmaxf(mx.x, __shfl_xor_sync(0xffffffffu, mx.x, o));
            mx.y = fmaxf(mx.y, __shfl_xor_sync(0xffffffffu, mx.y, o));
            mx.z = fmaxf(mx.z, __shfl_xor_sync(0xffffffffu, mx.z, o));
            mx.w = fmaxf(mx.w, __shfl_xor_sync(0xffffffffu, mx.w, o));
        }
        for (int c0 = beg; c0 < end; c0 += 32) {
            int e = c0 + lane;
            if (e < end) {
                int s = __ldg(&srcs[e]);
                float4 a = *(const float4*)(AS + s * 4);
                float t; float4 ex;
                t = a.x + ad.x; t = t > 0.f ? t : 0.2f * t; ex.x = __expf(t - mx.x);
                t = a.y + ad.y; t = t > 0.f ? t : 0.2f * t; ex.y = __expf(t - mx.y);
                t = a.z + ad.z; t = t > 0.f ? t : 0.2f * t; ex.z = __expf(t - mx.z);
                t = a.w + ad.w; t = t > 0.f ? t : 0.2f * t; ex.w = __expf(t - mx.w);
                den.x += ex.x; den.y += ex.y; den.z += ex.z; den.w += ex.w;
                ssrc[ws][lane] = s;
                slog[ws][lane] = ex;
            }
            __syncwarp();
            int cnt = min(32, end - c0);
            if (act) {
                const float* sexf = (const float*)&slog[ws][0];
                for (int j = 0; j < cnt; j++) {
                    int s = ssrc[ws][j];
                    float wv = sexf[j * 4 + head];
                    uint2 raw = __ldg((const uint2*)(H2 + s * 48) + lane);
                    float2 f01 = __half22float2(*(__half2*)&raw.x);
                    float2 f23 = __half22float2(*(__half2*)&raw.y);
                    acc.x = fmaf(f01.x, wv, acc.x);
                    acc.y = fmaf(f01.y, wv, acc.y);
                    acc.z = fmaf(f23.x, wv, acc.z);
                    acc.w = fmaf(f23.y, wv, acc.w);
                }
            }
            __syncwarp();
        }
#pragma unroll
        for (int o = 16; o > 0; o >>= 1) {
            den.x += __shfl_xor_sync(0xffffffffu, den.x, o);
            den.y += __shfl_xor_sync(0xffffffffu, den.y, o);
            den.z += __shfl_xor_sync(0xffffffffu, den.z, o);
            den.w += __shfl_xor_sync(0xffffffffu, den.w, o);
        }
        if (act) {
            float dh = head == 0 ? den.x : (head == 1 ? den.y : (head == 2 ? den.z : den.w));
            float inv = 1.f / (dh + 1e-16f);
            float4 b4 = *(const float4*)(bias + lane * 4);
            float4 o;
            o.x = acc.x * inv + b4.x;  o.x = o.x > 0.f ? o.x : expm1f(o.x);
            o.y = acc.y * inv + b4.y;  o.y = o.y > 0.f ? o.y : expm1f(o.y);
            o.z = acc.z * inv + b4.z;  o.z = o.z > 0.f ? o.z : expm1f(o.z);
            o.w = acc.w * inv + b4.w;  o.w = o.w > 0.f ? o.w : expm1f(o.w);
            *(float4*)(OUT + node * 96 + lane * 4) = o;
        }
    }
}

// ================= gate MLP as GEMM: [n,96]@[96,48] -> relu -> ·gw2 =================
__global__ void __launch_bounds__(384, 2) k_gateg(const float* __restrict__ O,
                                                  const float* __restrict__ gw1,
                                                  const float* __restrict__ gb1,
                                                  const float* __restrict__ gw2,
                                                  const float* __restrict__ gb2,
                                                  const int* __restrict__ batch,
                                                  float* __restrict__ GATE,
                                                  float* __restrict__ GM, int n) {
    extern __shared__ float sm[];
    float* Bs = sm;              // 96*48
    float* As = sm + 96 * 48;    // 96*193
    int tid = threadIdx.x;
    int w = tid >> 5, lane = tid & 31;
    int row0 = blockIdx.x * 192;

    ull acc[6][2];
#pragma unroll
    for (int f = 0; f < 6; f++) { acc[f][0] = 0ull; acc[f][1] = 0ull; }

    for (int i = tid; i < 96 * 48; i += 384) Bs[i] = gw1[i];
    for (int i = tid; i < 192 * 96; i += 384) {
        int k = i % 96, r = i / 96;
        int row = row0 + r;
        As[k * 193 + r] = (row < n) ? O[row * 96 + k] : 0.f;
    }
    __syncthreads();

#pragma unroll 8
    for (int k = 0; k < 96; k++) {
        const ull* b_ = (const ull*)&Bs[k * 48 + w * 4];
        ull bp0 = b_[0], bp1 = b_[1];
        const float* a_ = &As[k * 193 + lane];
#pragma unroll
        for (int f = 0; f < 6; f++) {
            float av = a_[f * 32];
            ull ap = pk2(av, av);
            acc[f][0] = fma2(ap, bp0, acc[f][0]);
            acc[f][1] = fma2(ap, bp1, acc[f][1]);
        }
    }

    float b1v[4], g2v[4];
#pragma unroll
    for (int jj = 0; jj < 4; jj++) {
        b1v[jj] = __ldg(&gb1[w * 4 + jj]);
        g2v[jj] = __ldg(&gw2[w * 4 + jj]);
    }
    float* sAl = sm;
    __syncthreads();
    for (int i = tid; i < 192; i += 384) sAl[i] = 0.f;
    __syncthreads();

#pragma unroll
    for (int f = 0; f < 6; f++) {
        int r = lane + f * 32;
        float h0, h1, h2, h3;
        upk2(acc[f][0], h0, h1);
        upk2(acc[f][1], h2, h3);
        float p = fmaxf(h0 + b1v[0], 0.f) * g2v[0]
                + fmaxf(h1 + b1v[1], 0.f) * g2v[1]
                + fmaxf(h2 + b1v[2], 0.f) * g2v[2]
                + fmaxf(h3 + b1v[3], 0.f) * g2v[3];
        atomicAdd(&sAl[r], p);
    }
    __syncthreads();
    float gb2v = __ldg(&gb2[0]);
    for (int i = tid; i < 192; i += 384) {
        int row = row0 + i;
        if (row < n) {
            float g = sAl[i] + gb2v;
            GATE[row] = g;
            atomicMaxF(&GM[__ldg(&batch[row])], g);
        }
    }
}

// ================= pooling: 8 blocks per graph; denom computed in-block =================
__global__ void k_pool2(const float* __restrict__ H, const float* __restrict__ GATE,
                        const float* __restrict__ GM, const int* __restrict__ batch,
                        float* __restrict__ POOL, int n) {
    __shared__ float red[192];
    __shared__ float sden;
    int g = blockIdx.x;
    int part = blockIdx.y;
    int tid = threadIdx.x;
    int lo = 0, hi = n;
    while (lo < hi) { int mid = (lo + hi) >> 1; if (__ldg(&batch[mid]) < g) lo = mid + 1; else hi = mid; }
    int beg = lo;
    lo = beg; hi = n;
    while (lo < hi) { int mid = (lo + hi) >> 1; if (__ldg(&batch[mid]) < g + 1) lo = mid + 1; else hi = mid; }
    int end = lo;

    float m = __ldg(&GM[g]);
    if (m == -INFINITY) m = 0.f;

    float dsum = 0.f;
    for (int node = beg + tid; node < end; node += 192)
        dsum += __expf(__ldg(&GATE[node]) - m);
    red[tid] = dsum;
    __syncthreads();
    if (tid < 96) red[tid] += red[tid + 96];
    __syncthreads();
    if (tid < 32) {
        float v = red[tid] + red[tid + 32] + red[tid + 64];
#pragma unroll
        for (int o = 16; o > 0; o >>= 1) v += __shfl_xor_sync(0xffffffffu, v, o);
        if (tid == 0) sden = v;
    }
    __syncthreads();
    float invden = 1.f / (sden + 1e-16f);

    int half = tid / 96, c = tid - half * 96;
    float acc = 0.f;
    for (int node = beg + part * 2 + half; node < end; node += 16) {
        float wv = __expf(__ldg(&GATE[node]) - m) * invden;
        acc = fmaf(__ldg(&H[node * 96 + c]), wv, acc);
    }
    __syncthreads();
    red[tid] = acc;
    __syncthreads();
    if (tid < 96) POOL[(g * 8 + part) * 96 + tid] = red[tid] + red[tid + 96];
}

__global__ void k_final(const float* __restrict__ POOL, const float* __restrict__ fw1,
                        const float* __restrict__ fb1, const float* __restrict__ fw2,
                        const float* __restrict__ fb2, float* __restrict__ out) {
    __shared__ float pr[96];
    __shared__ float hid[96];
    int g = blockIdx.x, j = threadIdx.x;
    float p = 0.f;
#pragma unroll
    for (int q = 0; q < 8; q++) p += POOL[(g * 8 + q) * 96 + j];
    pr[j] = p;
    __syncthreads();
    float a = fb1[j];
#pragma unroll 8
    for (int k = 0; k < 96; k++) a += pr[k] * fw1[k * 96 + j];
    hid[j] = fmaxf(a, 0.f);
    __syncthreads();
    if (j < 3) {
        float o = fb2[j];
        for (int k = 0; k < 96; k++) o += hid[k] * fw2[k * 3 + j];
        out[g * 3 + j] = o;
    }
}

// ================= host =================
extern "C" void kernel_launch(void* const* d_in, const int* in_sizes, int n_in,
                              void* d_out, int out_size) {
    const float* x     = (const float*)d_in[0];
    const int*   ei    = (const int*)d_in[1];
    const int*   batch = (const int*)d_in[2];
    int idx = 3;
    if (n_in > 3 && in_sizes[3] == 1) idx = 4;
    const float* W1  = (const float*)d_in[idx++];
    const float* as1 = (const float*)d_in[idx++];
    const float* ad1 = (const float*)d_in[idx++];
    const float* b1  = (const float*)d_in[idx++];
    const float* W2  = (const float*)d_in[idx++];
    const float* as2 = (const float*)d_in[idx++];
    const float* ad2 = (const float*)d_in[idx++];
    const float* b2  = (const float*)d_in[idx++];
    const float* gw1 = (const float*)d_in[idx++];
    const float* gb1 = (const float*)d_in[idx++];
    const float* gw2 = (const float*)d_in[idx++];
    const float* gb2 = (const float*)d_in[idx++];
    const float* fw1 = (const float*)d_in[idx++];
    const float* fb1 = (const float*)d_in[idx++];
    const float* fw2 = (const float*)d_in[idx++];
    const float* fb2 = (const float*)d_in[idx++];

    int n    = in_sizes[0] / 128;
    int eraw = in_sizes[1] / 2;
    int etot = eraw + n;

    float *o, *as_, *ad_, *gate, *gm, *gden, *pool;
    __half2* h2;
    int *deg, *part, *bsum, *off, *srcs;
    cudaGetSymbolAddress((void**)&h2,   d_h2);
    cudaGetSymbolAddress((void**)&o,    d_o);
    cudaGetSymbolAddress((void**)&as_,  d_as);
    cudaGetSymbolAddress((void**)&ad_,  d_ad);
    cudaGetSymbolAddress((void**)&gate, d_gate);
    cudaGetSymbolAddress((void**)&gm,   d_gm);
    cudaGetSymbolAddress((void**)&gden, d_gden);
    cudaGetSymbolAddress((void**)&pool, d_pool);
    cudaGetSymbolAddress((void**)&deg,  d_deg);
    cudaGetSymbolAddress((void**)&part, d_part);
    cudaGetSymbolAddress((void**)&bsum, d_bsum);
    cudaGetSymbolAddress((void**)&off,  d_off);
    cudaGetSymbolAddress((void**)&srcs, d_srcs);

    int smem1 = 128 * (128 + 8) * 2 + 128 * 104 * 2;
    int smem2 = 128 * 100 * 4;
    int smemG = (96 * 48 + 96 * 193) * 4;
    cudaFuncSetAttribute(k_gemmT<128>, cudaFuncAttributeMaxDynamicSharedMemorySize, smem1);
    cudaFuncSetAttribute(k_gemmT<96>,  cudaFuncAttributeMaxDynamicSharedMemorySize, smem2);
    cudaFuncSetAttribute(k_gateg,      cudaFuncAttributeMaxDynamicSharedMemorySize, smemG);

    int gEdge  = (etot + 255) / 256;
    int gWarp  = (n * 32 + 255) / 256;
    int gGemm  = (n + 127) / 128;
    int gGate  = (n + 191) / 192;
    int gScan  = (n + 1023) / 1024;

    static cudaStream_t s1 = nullptr;
    static cudaEvent_t evFork = nullptr, evJoin = nullptr;
    if (s1 == nullptr) {
        cudaStreamCreateWithFlags(&s1, cudaStreamNonBlocking);
        cudaEventCreateWithFlags(&evFork, cudaEventDisableTiming);
        cudaEventCreateWithFlags(&evJoin, cudaEventDisableTiming);
    }

    // ---- fork: CSR build on side stream, layer-1 GEMM on main stream ----
    cudaEventRecord(evFork, 0);
    cudaStreamWaitEvent(s1, evFork, 0);

    cudaMemsetAsync(deg, 0, n * sizeof(int), s1);
    k_hist<<<gEdge, 256, 0, s1>>>(ei, deg, etot, eraw);
    k_scanA<<<gScan, 1024, 0, s1>>>(deg, part, bsum, n);
    k_scanB<<<1, 64, 0, s1>>>(bsum, gScan);
    k_scanC<<<gScan, 1024, 0, s1>>>(part, bsum, off, deg, gm, gden, n, etot);
    k_scatter<<<gEdge, 256, 0, s1>>>(ei, deg, srcs, etot, eraw);
    cudaEventRecord(evJoin, s1);

    k_gemmT<128><<<gGemm, 256, smem1>>>(x, W1, as1, ad1, h2, as_, ad_, n);

    cudaStreamWaitEvent(0, evJoin, 0);
    k_sagg<<<gWarp, 256>>>(off, srcs, as_, ad_, h2, b1, o, n);

    k_gemmT<96><<<gGemm, 256, smem2>>>(o, W2, as2, ad2, h2, as_, ad_, n);
    k_sagg<<<gWarp, 256>>>(off, srcs, as_, ad_, h2, b2, o, n);

    k_gateg<<<gGate, 384, smemG>>>(o, gw1, gb1, gw2, gb2, batch, gate, gm, n);
    k_pool2<<<dim3(GG, 8), 192>>>(o, gate, gm, batch, pool, n);
    k_final<<<GG, 96>>>(pool, fw1, fb1, fw2, fb2, (float*)d_out);
}

// round 16
// speedup vs baseline: 1.0236x; 1.0236x over previous
#include <cuda_runtime.h>
#include <cuda_fp16.h>
#include <mma.h>
#include <math.h>

using namespace nvcuda;

#define NN 50000
#define EE 800000
#define ETOT (EE + NN)
#define GG 64

// ---------------- scratch ----------------
__device__ __half2 d_h2[NN * 48];
__device__ float d_o[NN * 96];
__device__ float d_as[NN * 4];
__device__ float d_ad[NN * 4];
__device__ int   d_deg[NN];          // statically zero-initialized; re-zeroed by k_tail each call
__device__ int   d_bsum[64];
__device__ int   d_flag;             // scan barrier flag; re-zeroed by k_tail
__device__ int   d_off[NN + 1];
__device__ int   d_srcs[ETOT];
__device__ float d_gate[NN];
__device__ float d_gm[GG];
__device__ float d_gden[GG];
__device__ float d_pool[GG * 8 * 96];

__device__ __forceinline__ void atomicMaxF(float* a, float v) {
    if (v >= 0.f) atomicMax((int*)a, __float_as_int(v));
    else          atomicMin((unsigned int*)a, __float_as_uint(v));
}

typedef unsigned long long ull;
__device__ __forceinline__ ull pk2(float x, float y) {
    ull r;
    asm("mov.b64 %0, {%1, %2};" : "=l"(r) : "f"(x), "f"(y));
    return r;
}
__device__ __forceinline__ ull fma2(ull a, ull b, ull c) {
    ull d;
    asm("fma.rn.f32x2 %0, %1, %2, %3;" : "=l"(d) : "l"(a), "l"(b), "l"(c));
    return d;
}
__device__ __forceinline__ void upk2(ull v, float& x, float& y) {
    asm("mov.b64 {%0, %1}, %2;" : "=f"(x), "=f"(y) : "l"(v));
}

// ================= CSR build =================
__global__ void k_hist(const int* __restrict__ ei, int* __restrict__ deg, int etot, int eraw) {
    int e = blockIdx.x * blockDim.x + threadIdx.x;
    if (e >= etot) return;
    int d = (e < eraw) ? __ldg(&ei[eraw + e]) : e - eraw;
    atomicAdd(&deg[d], 1);
}

// fused scan: per-block scan + spin-wait barrier + offset apply + GM/GDEN init.
// gridDim.x <= 148 so all blocks are resident -> spin is safe.
__global__ void k_scanF(const int* __restrict__ deg, int* __restrict__ off,
                        int* __restrict__ cur, int* __restrict__ bsum, int* __restrict__ flag,
                        float* __restrict__ GM, float* __restrict__ GDEN,
                        int n, int etot) {
    __shared__ int wsum[32];
    __shared__ int sOff;
    int t = threadIdx.x;
    int b = blockIdx.x;
    int i = b * 1024 + t;
    int v = (i < n) ? deg[i] : 0;
    int lane = t & 31, w = t >> 5;
    int x = v;
#pragma unroll
    for (int o = 1; o < 32; o <<= 1) {
        int y = __shfl_up_sync(0xffffffffu, x, o);
        if (lane >= o) x += y;
    }
    if (lane == 31) wsum[w] = x;
    __syncthreads();
    if (w == 0) {
        int s = wsum[lane];
#pragma unroll
        for (int o = 1; o < 32; o <<= 1) {
            int y = __shfl_up_sync(0xffffffffu, s, o);
            if (lane >= o) s += y;
        }
        wsum[lane] = s;
    }
    __syncthreads();
    int woff = (w > 0) ? wsum[w - 1] : 0;
    int local = x - v + woff;          // exclusive prefix within block

    if (t == 0) {
        bsum[b] = wsum[31];
        __threadfence();
        atomicAdd(flag, 1);
        while (atomicAdd(flag, 0) < (int)gridDim.x) { }
        int run = 0;
        volatile int* vb = (volatile int*)bsum;
        for (int q = 0; q < b; q++) run += vb[q];
        sOff = run;
    }
    __syncthreads();
    if (i < n) {
        int val = local + sOff;
        off[i] = val;
        cur[i] = val;
    }
    if (b == 0 && t == 0) off[n] = etot;
    if (b == 0 && t < GG) {
        GM[t] = -INFINITY;
        GDEN[t] = 0.f;
    }
}

__global__ void k_scatter(const int* __restrict__ ei, int* __restrict__ cur,
                          int* __restrict__ srcs, int etot, int eraw) {
    int e = blockIdx.x * blockDim.x + threadIdx.x;
    if (e >= etot) return;
    int s, d;
    if (e < eraw) { s = __ldg(&ei[e]); d = __ldg(&ei[eraw + e]); }
    else          { s = d = e - eraw; }
    int pos = atomicAdd(&cur[d], 1);
    srcs[pos] = s;
}

// tail: reset deg + flag for the NEXT replay (off the critical path)
__global__ void k_tail(int* __restrict__ deg, int* __restrict__ flag, int n) {
    int i = blockIdx.x * 1024 + threadIdx.x;
    if (i < n) deg[i] = 0;
    if (i == 0) *flag = 0;
}

// ================= Tensor-core GEMM + fused alpha epilogue =================
template<int K>
__global__ void __launch_bounds__(256, 2) k_gemmT(const float* __restrict__ A,
                                                  const float* __restrict__ W,
                                                  const float* __restrict__ asrc,
                                                  const float* __restrict__ adst,
                                                  __half2* __restrict__ H2,
                                                  float* __restrict__ AS,
                                                  float* __restrict__ AD, int n) {
    extern __shared__ char smc[];
    const int SA = K + 8, SB = 104, SC = 100;
    __half* Ah = (__half*)smc;
    __half* Wh = (__half*)smc + 128 * SA;
    float*  Cs = (float*)smc;
    __shared__ float s_as[96], s_ad[96];

    int tid = threadIdx.x, w = tid >> 5;
    int row0 = blockIdx.x * 128;

    if (tid < 96) { s_as[tid] = __ldg(&asrc[tid]); s_ad[tid] = __ldg(&adst[tid]); }

    for (int i = tid; i < 128 * K; i += 256) {
        int r = i / K, c = i - r * K;
        int row = row0 + r;
        Ah[r * SA + c] = (row < n) ? __float2half(A[(size_t)row * K + c]) : __half(0.f);
    }
    for (int i = tid; i < K * 96; i += 256) {
        int k = i / 96, c = i - k * 96;
        Wh[k * SB + c] = __float2half(W[i]);
    }
    __syncthreads();

    wmma::fragment<wmma::accumulator, 16, 16, 16, float> cf[6];
#pragma unroll
    for (int cg = 0; cg < 6; cg++) wmma::fill_fragment(cf[cg], 0.f);
    wmma::fragment<wmma::matrix_a, 16, 16, 16, __half, wmma::row_major> af;
    wmma::fragment<wmma::matrix_b, 16, 16, 16, __half, wmma::row_major> bf;
#pragma unroll
    for (int ks = 0; ks < K / 16; ks++) {
        wmma::load_matrix_sync(af, Ah + w * 16 * SA + ks * 16, SA);
#pragma unroll
        for (int cg = 0; cg < 6; cg++) {
            wmma::load_matrix_sync(bf, Wh + ks * 16 * SB + cg * 16, SB);
            wmma::mma_sync(cf[cg], af, bf, cf[cg]);
        }
    }
    __syncthreads();
#pragma unroll
    for (int cg = 0; cg < 6; cg++)
        wmma::store_matrix_sync(Cs + w * 16 * SC + cg * 16, cf[cg], SC, wmma::mem_row_major);
    __syncthreads();

    int row = tid >> 1, hv = tid & 1;
    int grow = row0 + row;
    if (grow < n) {
        const float* cr = Cs + row * SC + hv * 48;
        int h0 = hv * 2;
        const float* as0 = s_as + h0 * 24;
        const float* ad0 = s_ad + h0 * 24;
        union { __half2 h[24]; uint4 u[6]; } pk;
        float sp0 = 0.f, dp0 = 0.f, sp1 = 0.f, dp1 = 0.f;
#pragma unroll
        for (int j = 0; j < 12; j++) {
            float ca = cr[2 * j], cb = cr[2 * j + 1];
            pk.h[j] = __floats2half2_rn(ca, cb);
            sp0 += ca * as0[2 * j] + cb * as0[2 * j + 1];
            dp0 += ca * ad0[2 * j] + cb * ad0[2 * j + 1];
        }
#pragma unroll
        for (int j = 12; j < 24; j++) {
            float ca = cr[2 * j], cb = cr[2 * j + 1];
            pk.h[j] = __floats2half2_rn(ca, cb);
            int jj = 2 * j - 24;
            sp1 += ca * as0[24 + jj] + cb * as0[24 + jj + 1];
            dp1 += ca * ad0[24 + jj] + cb * ad0[24 + jj + 1];
        }
        uint4* dst = (uint4*)(H2 + (size_t)grow * 48 + hv * 24);
#pragma unroll
        for (int q = 0; q < 6; q++) dst[q] = pk.u[q];
        AS[grow * 4 + h0]     = sp0;
        AS[grow * 4 + h0 + 1] = sp1;
        AD[grow * 4 + h0]     = dp0;
        AD[grow * 4 + h0 + 1] = dp1;
    }
}

// ================= fused softmax + aggregation (warp per dst, uint2 gather) =================
#define DCAP 128
__global__ void k_sagg(const int* __restrict__ off, const int* __restrict__ srcs,
                       const float* __restrict__ AS, const float* __restrict__ AD,
                       const __half2* __restrict__ H2, const float* __restrict__ bias,
                       float* __restrict__ OUT, int n) {
    __shared__ int    ssrc[8][DCAP];
    __shared__ float4 slog[8][DCAP];
    int gtid = blockIdx.x * blockDim.x + threadIdx.x;
    int node = gtid >> 5, lane = gtid & 31;
    int ws = threadIdx.x >> 5;
    if (node >= n) return;
    int beg = __ldg(&off[node]), end = __ldg(&off[node + 1]);
    int deg = end - beg;
    float4 ad = *(const float4*)(AD + node * 4);

    bool act = lane < 24;
    int head = lane / 6;
    float4 acc = make_float4(0.f, 0.f, 0.f, 0.f);
    float4 den = make_float4(0.f, 0.f, 0.f, 0.f);
    float4 mx = make_float4(-INFINITY, -INFINITY, -INFINITY, -INFINITY);

    if (deg <= DCAP) {
        for (int j = lane; j < deg; j += 32) {
            int s = __ldg(&srcs[beg + j]);
            float4 a = *(const float4*)(AS + s * 4);
            float t; float4 v;
            t = a.x + ad.x; v.x = t > 0.f ? t : 0.2f * t; mx.x = fmaxf(mx.x, v.x);
            t = a.y + ad.y; v.y = t > 0.f ? t : 0.2f * t; mx.y = fmaxf(mx.y, v.y);
            t = a.z + ad.z; v.z = t > 0.f ? t : 0.2f * t; mx.z = fmaxf(mx.z, v.z);
            t = a.w + ad.w; v.w = t > 0.f ? t : 0.2f * t; mx.w = fmaxf(mx.w, v.w);
            ssrc[ws][j] = s;
            slog[ws][j] = v;
        }
#pragma unroll
        for (int o = 16; o > 0; o >>= 1) {
            mx.x = fmaxf(mx.x, __shfl_xor_sync(0xffffffffu, mx.x, o));
            mx.y = fmaxf(mx.y, __shfl_xor_sync(0xffffffffu, mx.y, o));
            mx.z = fmaxf(mx.z, __shfl_xor_sync(0xffffffffu, mx.z, o));
            mx.w = fmaxf(mx.w, __shfl_xor_sync(0xffffffffu, mx.w, o));
        }
        __syncwarp();
        for (int j = lane; j < deg; j += 32) {
            float4 v = slog[ws][j];
            float4 ex;
            ex.x = __expf(v.x - mx.x); ex.y = __expf(v.y - mx.y);
            ex.z = __expf(v.z - mx.z); ex.w = __expf(v.w - mx.w);
            slog[ws][j] = ex;
            den.x += ex.x; den.y += ex.y; den.z += ex.z; den.w += ex.w;
        }
        __syncwarp();
        if (act) {
            const float* sexf = (const float*)&slog[ws][0];
#pragma unroll 4
            for (int j = 0; j < deg; j++) {
                int s = ssrc[ws][j];
                float wv = sexf[j * 4 + head];
                uint2 raw = __ldg((const uint2*)(H2 + s * 48) + lane);
                float2 f01 = __half22float2(*(__half2*)&raw.x);
                float2 f23 = __half22float2(*(__half2*)&raw.y);
                acc.x = fmaf(f01.x, wv, acc.x);
                acc.y = fmaf(f01.y, wv, acc.y);
                acc.z = fmaf(f23.x, wv, acc.z);
                acc.w = fmaf(f23.y, wv, acc.w);
            }
        }
    } else {
        for (int e = beg + lane; e < end; e += 32) {
            int s = __ldg(&srcs[e]);
            float4 a = *(const float4*)(AS + s * 4);
            float t;
            t = a.x + ad.x; t = t > 0.f ? t : 0.2f * t; mx.x = fmaxf(mx.x, t);
            t = a.y + ad.y; t = t > 0.f ? t : 0.2f * t; mx.y = fmaxf(mx.y, t);
            t = a.z + ad.z; t = t > 0.f ? t : 0.2f * t; mx.z = fmaxf(mx.z, t);
            t = a.w + ad.w; t = t > 0.f ? t : 0.2f * t; mx.w = fmaxf(mx.w, t);
        }
#pragma unroll
        for (int o = 16; o > 0; o >>= 1) {
            mx.x = fmaxf(mx.x, __shfl_xor_sync(0xffffffffu, mx.x, o));
            mx.y = fmaxf(mx.y, __shfl_xor_sync(0xffffffffu, mx.y, o));
            mx.z = fmaxf(mx.z, __shfl_xor_sync(0xffffffffu, mx.z, o));
            mx.w = fmaxf(mx.w, __shfl_xor_sync(0xffffffffu, mx.w, o));
        }
        for (int c0 = beg; c0 < end; c0 += 32) {
            int e = c0 + lane;
            if (e < end) {
                int s = __ldg(&srcs[e]);
                float4 a = *(const float4*)(AS + s * 4);
                float t; float4 ex;
                t = a.x + ad.x; t = t > 0.f ? t : 0.2f * t; ex.x = __expf(t - mx.x);
                t = a.y + ad.y; t = t > 0.f ? t : 0.2f * t; ex.y = __expf(t - mx.y);
                t = a.z + ad.z; t = t > 0.f ? t : 0.2f * t; ex.z = __expf(t - mx.z);
                t = a.w + ad.w; t = t > 0.f ? t : 0.2f * t; ex.w = __expf(t - mx.w);
                den.x += ex.x; den.y += ex.y; den.z += ex.z; den.w += ex.w;
                ssrc[ws][lane] = s;
                slog[ws][lane] = ex;
            }
            __syncwarp();
            int cnt = min(32, end - c0);
            if (act) {
                const float* sexf = (const float*)&slog[ws][0];
                for (int j = 0; j < cnt; j++) {
                    int s = ssrc[ws][j];
                    float wv = sexf[j * 4 + head];
                    uint2 raw = __ldg((const uint2*)(H2 + s * 48) + lane);
                    float2 f01 = __half22float2(*(__half2*)&raw.x);
                    float2 f23 = __half22float2(*(__half2*)&raw.y);
                    acc.x = fmaf(f01.x, wv, acc.x);
                    acc.y = fmaf(f01.y, wv, acc.y);
                    acc.z = fmaf(f23.x, wv, acc.z);
                    acc.w = fmaf(f23.y, wv, acc.w);
                }
            }
            __syncwarp();
        }
    }

#pragma unroll
    for (int o = 16; o > 0; o >>= 1) {
        den.x += __shfl_xor_sync(0xffffffffu, den.x, o);
        den.y += __shfl_xor_sync(0xffffffffu, den.y, o);
        den.z += __shfl_xor_sync(0xffffffffu, den.z, o);
        den.w += __shfl_xor_sync(0xffffffffu, den.w, o);
    }
    if (act) {
        float dh = head == 0 ? den.x : (head == 1 ? den.y : (head == 2 ? den.z : den.w));
        float inv = 1.f / (dh + 1e-16f);
        float4 b4 = *(const float4*)(bias + lane * 4);
        float4 o;
        o.x = acc.x * inv + b4.x;  o.x = o.x > 0.f ? o.x : expm1f(o.x);
        o.y = acc.y * inv + b4.y;  o.y = o.y > 0.f ? o.y : expm1f(o.y);
        o.z = acc.z * inv + b4.z;  o.z = o.z > 0.f ? o.z : expm1f(o.z);
        o.w = acc.w * inv + b4.w;  o.w = o.w > 0.f ? o.w : expm1f(o.w);
        *(float4*)(OUT + node * 96 + lane * 4) = o;
    }
}

// ================= gate MLP as GEMM =================
__global__ void __launch_bounds__(384, 2) k_gateg(const float* __restrict__ O,
                                                  const float* __restrict__ gw1,
                                                  const float* __restrict__ gb1,
                                                  const float* __restrict__ gw2,
                                                  const float* __restrict__ gb2,
                                                  const int* __restrict__ batch,
                                                  float* __restrict__ GATE,
                                                  float* __restrict__ GM, int n) {
    extern __shared__ float sm[];
    float* Bs = sm;
    float* As = sm + 96 * 48;
    int tid = threadIdx.x;
    int w = tid >> 5, lane = tid & 31;
    int row0 = blockIdx.x * 192;

    ull acc[6][2];
#pragma unroll
    for (int f = 0; f < 6; f++) { acc[f][0] = 0ull; acc[f][1] = 0ull; }

    for (int i = tid; i < 96 * 48; i += 384) Bs[i] = gw1[i];
    for (int i = tid; i < 192 * 96; i += 384) {
        int k = i % 96, r = i / 96;
        int row = row0 + r;
        As[k * 193 + r] = (row < n) ? O[row * 96 + k] : 0.f;
    }
    __syncthreads();

#pragma unroll 8
    for (int k = 0; k < 96; k++) {
        const ull* b_ = (const ull*)&Bs[k * 48 + w * 4];
        ull bp0 = b_[0], bp1 = b_[1];
        const float* a_ = &As[k * 193 + lane];
#pragma unroll
        for (int f = 0; f < 6; f++) {
            float av = a_[f * 32];
            ull ap = pk2(av, av);
            acc[f][0] = fma2(ap, bp0, acc[f][0]);
            acc[f][1] = fma2(ap, bp1, acc[f][1]);
        }
    }

    float b1v[4], g2v[4];
#pragma unroll
    for (int jj = 0; jj < 4; jj++) {
        b1v[jj] = __ldg(&gb1[w * 4 + jj]);
        g2v[jj] = __ldg(&gw2[w * 4 + jj]);
    }
    float* sAl = sm;
    __syncthreads();
    for (int i = tid; i < 192; i += 384) sAl[i] = 0.f;
    __syncthreads();

#pragma unroll
    for (int f = 0; f < 6; f++) {
        int r = lane + f * 32;
        float h0, h1, h2, h3;
        upk2(acc[f][0], h0, h1);
        upk2(acc[f][1], h2, h3);
        float p = fmaxf(h0 + b1v[0], 0.f) * g2v[0]
                + fmaxf(h1 + b1v[1], 0.f) * g2v[1]
                + fmaxf(h2 + b1v[2], 0.f) * g2v[2]
                + fmaxf(h3 + b1v[3], 0.f) * g2v[3];
        atomicAdd(&sAl[r], p);
    }
    __syncthreads();
    float gb2v = __ldg(&gb2[0]);
    for (int i = tid; i < 192; i += 384) {
        int row = row0 + i;
        if (row < n) {
            float g = sAl[i] + gb2v;
            GATE[row] = g;
            atomicMaxF(&GM[__ldg(&batch[row])], g);
        }
    }
}

// ================= pooling =================
__global__ void k_pool2(const float* __restrict__ H, const float* __restrict__ GATE,
                        const float* __restrict__ GM, const int* __restrict__ batch,
                        float* __restrict__ POOL, int n) {
    __shared__ float red[192];
    __shared__ float sden;
    int g = blockIdx.x;
    int part = blockIdx.y;
    int tid = threadIdx.x;
    int lo = 0, hi = n;
    while (lo < hi) { int mid = (lo + hi) >> 1; if (__ldg(&batch[mid]) < g) lo = mid + 1; else hi = mid; }
    int beg = lo;
    lo = beg; hi = n;
    while (lo < hi) { int mid = (lo + hi) >> 1; if (__ldg(&batch[mid]) < g + 1) lo = mid + 1; else hi = mid; }
    int end = lo;

    float m = __ldg(&GM[g]);
    if (m == -INFINITY) m = 0.f;

    float dsum = 0.f;
    for (int node = beg + tid; node < end; node += 192)
        dsum += __expf(__ldg(&GATE[node]) - m);
    red[tid] = dsum;
    __syncthreads();
    if (tid < 96) red[tid] += red[tid + 96];
    __syncthreads();
    if (tid < 32) {
        float v = red[tid] + red[tid + 32] + red[tid + 64];
#pragma unroll
        for (int o = 16; o > 0; o >>= 1) v += __shfl_xor_sync(0xffffffffu, v, o);
        if (tid == 0) sden = v;
    }
    __syncthreads();
    float invden = 1.f / (sden + 1e-16f);

    int half = tid / 96, c = tid - half * 96;
    float acc = 0.f;
    for (int node = beg + part * 2 + half; node < end; node += 16) {
        float wv = __expf(__ldg(&GATE[node]) - m) * invden;
        acc = fmaf(__ldg(&H[node * 96 + c]), wv, acc);
    }
    __syncthreads();
    red[tid] = acc;
    __syncthreads();
    if (tid < 96) POOL[(g * 8 + part) * 96 + tid] = red[tid] + red[tid + 96];
}

__global__ void k_final(const float* __restrict__ POOL, const float* __restrict__ fw1,
                        const float* __restrict__ fb1, const float* __restrict__ fw2,
                        const float* __restrict__ fb2, float* __restrict__ out) {
    __shared__ float pr[96];
    __shared__ float hid[96];
    int g = blockIdx.x, j = threadIdx.x;
    float p = 0.f;
#pragma unroll
    for (int q = 0; q < 8; q++) p += POOL[(g * 8 + q) * 96 + j];
    pr[j] = p;
    __syncthreads();
    float a = fb1[j];
#pragma unroll 8
    for (int k = 0; k < 96; k++) a += pr[k] * fw1[k * 96 + j];
    hid[j] = fmaxf(a, 0.f);
    __syncthreads();
    if (j < 3) {
        float o = fb2[j];
        for (int k = 0; k < 96; k++) o += hid[k] * fw2[k * 3 + j];
        out[g * 3 + j] = o;
    }
}

// ================= host =================
extern "C" void kernel_launch(void* const* d_in, const int* in_sizes, int n_in,
                              void* d_out, int out_size) {
    const float* x     = (const float*)d_in[0];
    const int*   ei    = (const int*)d_in[1];
    const int*   batch = (const int*)d_in[2];
    int idx = 3;
    if (n_in > 3 && in_sizes[3] == 1) idx = 4;
    const float* W1  = (const float*)d_in[idx++];
    const float* as1 = (const float*)d_in[idx++];
    const float* ad1 = (const float*)d_in[idx++];
    const float* b1  = (const float*)d_in[idx++];
    const float* W2  = (const float*)d_in[idx++];
    const float* as2 = (const float*)d_in[idx++];
    const float* ad2 = (const float*)d_in[idx++];
    const float* b2  = (const float*)d_in[idx++];
    const float* gw1 = (const float*)d_in[idx++];
    const float* gb1 = (const float*)d_in[idx++];
    const float* gw2 = (const float*)d_in[idx++];
    const float* gb2 = (const float*)d_in[idx++];
    const float* fw1 = (const float*)d_in[idx++];
    const float* fb1 = (const float*)d_in[idx++];
    const float* fw2 = (const float*)d_in[idx++];
    const float* fb2 = (const float*)d_in[idx++];

    int n    = in_sizes[0] / 128;
    int eraw = in_sizes[1] / 2;
    int etot = eraw + n;

    float *o, *as_, *ad_, *gate, *gm, *gden, *pool;
    __half2* h2;
    int *deg, *bsum, *flag, *off, *srcs;
    cudaGetSymbolAddress((void**)&h2,   d_h2);
    cudaGetSymbolAddress((void**)&o,    d_o);
    cudaGetSymbolAddress((void**)&as_,  d_as);
    cudaGetSymbolAddress((void**)&ad_,  d_ad);
    cudaGetSymbolAddress((void**)&gate, d_gate);
    cudaGetSymbolAddress((void**)&gm,   d_gm);
    cudaGetSymbolAddress((void**)&gden, d_gden);
    cudaGetSymbolAddress((void**)&pool, d_pool);
    cudaGetSymbolAddress((void**)&deg,  d_deg);
    cudaGetSymbolAddress((void**)&bsum, d_bsum);
    cudaGetSymbolAddress((void**)&flag, d_flag);
    cudaGetSymbolAddress((void**)&off,  d_off);
    cudaGetSymbolAddress((void**)&srcs, d_srcs);

    int smem1 = 128 * (128 + 8) * 2 + 128 * 104 * 2;
    int smem2 = 128 * 100 * 4;
    int smemG = (96 * 48 + 96 * 193) * 4;
    cudaFuncSetAttribute(k_gemmT<128>, cudaFuncAttributeMaxDynamicSharedMemorySize, smem1);
    cudaFuncSetAttribute(k_gemmT<96>,  cudaFuncAttributeMaxDynamicSharedMemorySize, smem2);
    cudaFuncSetAttribute(k_gateg,      cudaFuncAttributeMaxDynamicSharedMemorySize, smemG);

    int gEdge  = (etot + 255) / 256;
    int gWarp  = (n * 32 + 255) / 256;
    int gGemm  = (n + 127) / 128;
    int gGate  = (n + 191) / 192;
    int gScan  = (n + 1023) / 1024;     // 49 <= 148 -> scanF spin barrier is safe

    static cudaStream_t s1 = nullptr;
    static cudaEvent_t evFork = nullptr, evJoin = nullptr, evTail = nullptr;
    if (s1 == nullptr) {
        cudaStreamCreateWithFlags(&s1, cudaStreamNonBlocking);
        cudaEventCreateWithFlags(&evFork, cudaEventDisableTiming);
        cudaEventCreateWithFlags(&evJoin, cudaEventDisableTiming);
        cudaEventCreateWithFlags(&evTail, cudaEventDisableTiming);
    }

    // ---- fork: CSR build on side stream, layer-1 GEMM on main stream ----
    cudaEventRecord(evFork, 0);
    cudaStreamWaitEvent(s1, evFork, 0);

    k_hist<<<gEdge, 256, 0, s1>>>(ei, deg, etot, eraw);
    k_scanF<<<gScan, 1024, 0, s1>>>(deg, off, deg, bsum, flag, gm, gden, n, etot);
    k_scatter<<<gEdge, 256, 0, s1>>>(ei, deg, srcs, etot, eraw);
    cudaEventRecord(evJoin, s1);
    k_tail<<<gScan, 1024, 0, s1>>>(deg, flag, n);   // reset for next replay, off critical path
    cudaEventRecord(evTail, s1);                    // side stream fully joined below

    k_gemmT<128><<<gGemm, 256, smem1>>>(x, W1, as1, ad1, h2, as_, ad_, n);

    cudaStreamWaitEvent(0, evJoin, 0);
    k_sagg<<<gWarp, 256>>>(off, srcs, as_, ad_, h2, b1, o, n);

    k_gemmT<96><<<gGemm, 256, smem2>>>(o, W2, as2, ad2, h2, as_, ad_, n);
    k_sagg<<<gWarp, 256>>>(off, srcs, as_, ad_, h2, b2, o, n);

    k_gateg<<<gGate, 384, smemG>>>(o, gw1, gb1, gw2, gb2, batch, gate, gm, n);
    k_pool2<<<dim3(GG, 8), 192>>>(o, gate, gm, batch, pool, n);
    cudaStreamWaitEvent(0, evTail, 0);              // join tail so capture graph is well-formed
    k_final<<<GG, 96>>>(pool, fw1, fb1, fw2, fb2, (float*)d_out);
}